// round 7
// baseline (speedup 1.0000x reference)
#include <cuda_runtime.h>
#include <cuda_bf16.h>
#include <cstdint>
#include <math.h>

// ---------------- problem constants ----------------
#define BATCH 32
#define HW    1024
#define C     512
#define GROUPS 32
#define CPG   16
#define M_TOT (BATCH*HW)       // 32768
#define EPS   1e-6f
#define NQKV  1536

// ---------------- scratch ----------------
__device__ __nv_bfloat16 g_hn  [(long long)M_TOT * C];
__device__ __nv_bfloat16 g_qkv [(long long)M_TOT * NQKV];    // [row][q|k|v]
__device__ __nv_bfloat16 g_s   [(long long)BATCH * HW * HW]; // exp(scores), unnormalized
__device__ __nv_bfloat16 g_o   [(long long)M_TOT * C];
__device__ __nv_bfloat16 g_wqkv[(long long)C * NQKV];        // [k][q|k|v]
__device__ __nv_bfloat16 g_wp  [(long long)C * C];
__device__ float g_bqkv[NQKV];
__device__ float g_rowsum[BATCH * HW];
__device__ float g_mean[BATCH * GROUPS];
__device__ float g_rstd[BATCH * GROUPS];

// ---------------- helpers ----------------
__device__ __forceinline__ uint32_t smem_u32(const void* p) {
    uint32_t a;
    asm("{ .reg .u64 t; cvta.to.shared.u64 t, %1; cvt.u32.u64 %0, t; }" : "=r"(a) : "l"(p));
    return a;
}
#define LDSM_X4(r0,r1,r2,r3,addr) \
    asm volatile("ldmatrix.sync.aligned.m8n8.x4.shared.b16 {%0,%1,%2,%3}, [%4];" \
        : "=r"(r0),"=r"(r1),"=r"(r2),"=r"(r3) : "r"(addr))
#define LDSM_X4T(r0,r1,r2,r3,addr) \
    asm volatile("ldmatrix.sync.aligned.m8n8.x4.trans.shared.b16 {%0,%1,%2,%3}, [%4];" \
        : "=r"(r0),"=r"(r1),"=r"(r2),"=r"(r3) : "r"(addr))
#define MMA_BF16(d, a, b) \
    asm volatile("mma.sync.aligned.m16n8k16.row.col.f32.bf16.bf16.f32 " \
        "{%0,%1,%2,%3}, {%4,%5,%6,%7}, {%8,%9}, {%0,%1,%2,%3};" \
        : "+f"((d)[0]), "+f"((d)[1]), "+f"((d)[2]), "+f"((d)[3]) \
        : "r"((a)[0]), "r"((a)[1]), "r"((a)[2]), "r"((a)[3]), "r"((b)[0]), "r"((b)[1]))
#define CP_ASYNC16(smem, gmem) \
    asm volatile("cp.async.cg.shared.global [%0], [%1], 16;" :: "r"(smem), "l"(gmem))
#define CP_COMMIT() asm volatile("cp.async.commit_group;" ::: "memory")
#define CP_WAIT1()  asm volatile("cp.async.wait_group 1;" ::: "memory")

// ---------------- groupnorm stats (float4) ----------------
__global__ __launch_bounds__(256)
void gn_stats_kernel(const float* __restrict__ x, float* __restrict__ mean, float* __restrict__ rstd)
{
    int bg = blockIdx.x, b = bg >> 5, g = bg & 31;
    const float4* base4 = reinterpret_cast<const float4*>(x + (long long)b * HW * C + g * CPG);
    float s = 0.f, s2 = 0.f;
    for (int e = threadIdx.x; e < HW * 4; e += 256) {
        int p = e >> 2, cc = e & 3;
        float4 v = base4[(long long)p * 128 + cc];
        s  += v.x + v.y + v.z + v.w;
        s2 += v.x * v.x + v.y * v.y + v.z * v.z + v.w * v.w;
    }
    __shared__ float sh1[256], sh2[256];
    sh1[threadIdx.x] = s; sh2[threadIdx.x] = s2;
    __syncthreads();
    for (int off = 128; off > 0; off >>= 1) {
        if (threadIdx.x < off) { sh1[threadIdx.x] += sh1[threadIdx.x + off]; sh2[threadIdx.x] += sh2[threadIdx.x + off]; }
        __syncthreads();
    }
    if (threadIdx.x == 0) {
        float m = sh1[0] * (1.f / (HW * CPG));
        float var = sh2[0] * (1.f / (HW * CPG)) - m * m;
        mean[bg] = m; rstd[bg] = rsqrtf(var + EPS);
    }
}

// ---------------- groupnorm apply -> bf16 (coalesced) ----------------
__global__ __launch_bounds__(256)
void gn_apply_kernel(const float* __restrict__ x, const float* __restrict__ scale,
                     const float* __restrict__ bias, const float* __restrict__ mean,
                     const float* __restrict__ rstd, __nv_bfloat16* __restrict__ hn)
{
    long long i = (long long)blockIdx.x * blockDim.x + threadIdx.x;
    const long long N4 = (long long)M_TOT * C / 4;
    if (i >= N4) return;
    int c4 = (int)(i & 127), c = c4 * 4;
    long long pix = i >> 7;
    int b = (int)(pix >> 10);
    int bg = b * GROUPS + (c >> 4);
    float m = mean[bg], r = rstd[bg];
    float4 v = reinterpret_cast<const float4*>(x)[i];
    float4 sc = reinterpret_cast<const float4*>(scale)[c4];
    float4 bi = reinterpret_cast<const float4*>(bias)[c4];
    __nv_bfloat162* h2 = reinterpret_cast<__nv_bfloat162*>(hn) + i * 2;
    h2[0] = __floats2bfloat162_rn((v.x - m) * r * sc.x + bi.x, (v.y - m) * r * sc.y + bi.y);
    h2[1] = __floats2bfloat162_rn((v.z - m) * r * sc.z + bi.z, (v.w - m) * r * sc.w + bi.w);
}

// ---------------- zero rowsum ----------------
__global__ __launch_bounds__(256)
void zero_rs_kernel(float* __restrict__ rs)
{
    int i = blockIdx.x * 256 + threadIdx.x;
    if (i < BATCH * HW) rs[i] = 0.f;
}

// ---------------- pack qkv weights -> bf16 [k][q|k|v] ----------------
__global__ __launch_bounds__(256)
void pack_qkvw_kernel(const float* __restrict__ wq, const float* __restrict__ wk,
                      const float* __restrict__ wv, __nv_bfloat16* __restrict__ o)
{
    int i = blockIdx.x * 256 + threadIdx.x;
    const int TOT = C * NQKV / 4;
    if (i >= TOT) return;
    int row = i / (NQKV / 4);
    int col = (i % (NQKV / 4)) * 4;
    int sel = col >> 9;
    const float* src = (sel == 0) ? wq : (sel == 1) ? wk : wv;
    float4 v = *reinterpret_cast<const float4*>(src + (long long)row * C + (col & 511));
    __nv_bfloat162* h2 = reinterpret_cast<__nv_bfloat162*>(o) + i * 2;
    h2[0] = __floats2bfloat162_rn(v.x, v.y);
    h2[1] = __floats2bfloat162_rn(v.z, v.w);
}

__global__ void pack_misc_kernel(const float* __restrict__ bq, const float* __restrict__ bk,
                                 const float* __restrict__ bv, float* __restrict__ bqkv,
                                 const float* __restrict__ wp, __nv_bfloat16* __restrict__ wpo)
{
    int i = blockIdx.x * 256 + threadIdx.x;
    if (i < NQKV) {
        int sel = i >> 9;
        const float* src = (sel == 0) ? bq : (sel == 1) ? bk : bv;
        bqkv[i] = src[i & 511];
    }
    if (i < C * C / 4) {
        float4 v = reinterpret_cast<const float4*>(wp)[i];
        __nv_bfloat162* h2 = reinterpret_cast<__nv_bfloat162*>(wpo) + i * 2;
        h2[0] = __floats2bfloat162_rn(v.x, v.y);
        h2[1] = __floats2bfloat162_rn(v.z, v.w);
    }
}

// ---------------- HMMA GEMM (256 threads, 8 warps of 32x64, 3-stage) ----------------
// TB=false (NT): D = A[M,K] @ B[N,K]^T.  TB=true (NN): D = A[M,K] @ B[K,N].
// MODE 0: bf16 out (+bias, *scale).
// MODE 1: bf16 out = exp(acc*scale), atomicAdd per-row sums into rowsum.
// MODE 2: fp32 out + bias + residual.
// MODE 3: bf16 out = acc / rowsum[row].
#define A_STRIDE 144u
#define BNN_STRIDE 272u
#define BOFF  18432u
#define STAGE 36864u
#define NSTG  3

template<bool TB, int MODE>
__global__ void __launch_bounds__(256, 2)
mma_gemm(const __nv_bfloat16* __restrict__ A, const __nv_bfloat16* __restrict__ B,
         const float* __restrict__ bias, const float* __restrict__ residual,
         float* __restrict__ rowsum,
         void* __restrict__ Out, int K, int lda, int ldb, int Ntot,
         float scale, long long sA, long long sB, long long sO)
{
    extern __shared__ char dyn[];
    const uint32_t smem0 = smem_u32(dyn);

    const int tid = threadIdx.x, lane = tid & 31, wid = tid >> 5;
    const int warp_m = wid & 3, warp_n = wid >> 2;
    const int bx = blockIdx.x, by = blockIdx.y, bz = blockIdx.z;

    const char* gA = (const char*)(A + bz * sA);
    const char* gB = (const char*)(B + bz * sB);

    const int NC = K >> 6;

    float acc[2][8][4];
#pragma unroll
    for (int mt = 0; mt < 2; mt++)
#pragma unroll
        for (int nt = 0; nt < 8; nt++)
#pragma unroll
            for (int e = 0; e < 4; e++) acc[mt][nt][e] = 0.f;

    auto load_chunk = [&](int ci) {
        const uint32_t st = smem0 + (uint32_t)(ci % NSTG) * STAGE;
#pragma unroll
        for (int rep = 0; rep < 4; rep++) {
            int c = tid + rep * 256;
            int row = c >> 3, cc = c & 7;
            uint32_t sa = st + (uint32_t)row * A_STRIDE + (uint32_t)cc * 16;
            const char* ga = gA + ((long long)(by * 128 + row) * lda) * 2 + (long long)ci * 128 + cc * 16;
            CP_ASYNC16(sa, ga);
        }
        if (TB) {
#pragma unroll
            for (int rep = 0; rep < 4; rep++) {
                int c = tid + rep * 256;
                int row = c >> 4, cc = c & 15;
                uint32_t sb = st + BOFF + (uint32_t)row * BNN_STRIDE + (uint32_t)cc * 16;
                const char* gb = gB + (((long long)(ci * 64 + row) * ldb) + bx * 128) * 2 + cc * 16;
                CP_ASYNC16(sb, gb);
            }
        } else {
#pragma unroll
            for (int rep = 0; rep < 4; rep++) {
                int c = tid + rep * 256;
                int row = c >> 3, cc = c & 7;
                uint32_t sb = st + BOFF + (uint32_t)row * A_STRIDE + (uint32_t)cc * 16;
                const char* gb = gB + ((long long)(bx * 128 + row) * ldb) * 2 + (long long)ci * 128 + cc * 16;
                CP_ASYNC16(sb, gb);
            }
        }
        CP_COMMIT();
    };

    load_chunk(0);
    load_chunk(1);

    const int lan15 = lane & 15;
    const int hi8   = (lane >> 4) << 3;

    for (int i = 0; i < NC; ++i) {
        CP_WAIT1();
        __syncthreads();
        // prefetch chunk i+2 right after the barrier: stage (i+2)%3 == (i-1)%3,
        // whose readers (iteration i-1 compute) all passed the barrier above.
        int nc = i + 2;
        if (nc < NC) load_chunk(nc);
        else CP_COMMIT();

        const uint32_t smA = smem0 + (uint32_t)(i % NSTG) * STAGE;
        const uint32_t smB = smA + BOFF;
#pragma unroll
        for (int ks = 0; ks < 4; ks++) {
            uint32_t a[2][4];
#pragma unroll
            for (int mt = 0; mt < 2; mt++) {
                uint32_t ad = smA + (uint32_t)(warp_m * 32 + mt * 16 + lan15) * A_STRIDE
                                  + (uint32_t)(ks * 16 + hi8) * 2;
                LDSM_X4(a[mt][0], a[mt][1], a[mt][2], a[mt][3], ad);
            }
            uint32_t b[8][2];
            if (TB) {
#pragma unroll
                for (int np = 0; np < 4; np++) {
                    uint32_t ad = smB + (uint32_t)(ks * 16 + lan15) * BNN_STRIDE
                                      + (uint32_t)(warp_n * 64 + np * 16 + hi8) * 2;
                    uint32_t r0, r1, r2, r3;
                    LDSM_X4T(r0, r1, r2, r3, ad);
                    b[2*np][0] = r0; b[2*np][1] = r1;
                    b[2*np+1][0] = r2; b[2*np+1][1] = r3;
                }
            } else {
#pragma unroll
                for (int np = 0; np < 4; np++) {
                    uint32_t ad = smB + (uint32_t)(warp_n * 64 + np * 16 + lan15) * A_STRIDE
                                      + (uint32_t)(ks * 16 + hi8) * 2;
                    uint32_t r0, r1, r2, r3;
                    LDSM_X4(r0, r1, r2, r3, ad);
                    b[2*np][0] = r0; b[2*np][1] = r2;
                    b[2*np+1][0] = r1; b[2*np+1][1] = r3;
                }
            }
#pragma unroll
            for (int mt = 0; mt < 2; mt++)
#pragma unroll
                for (int nt = 0; nt < 8; nt++)
                    MMA_BF16(acc[mt][nt], a[mt], b[nt]);
        }
    }

    // ---------------- epilogue ----------------
    const int group = lane >> 2, tig = lane & 3;
#pragma unroll
    for (int mt = 0; mt < 2; mt++) {
        const int r0 = by * 128 + warp_m * 32 + mt * 16 + group;
        if (MODE == 1) {
            __nv_bfloat16* op = (__nv_bfloat16*)Out + bz * sO;
            float rs0 = 0.f, rs1 = 0.f;
#pragma unroll
            for (int nt = 0; nt < 8; nt++) {
                const int cg = bx * 128 + warp_n * 64 + nt * 8 + tig * 2;
                float e0 = __expf(acc[mt][nt][0] * scale);
                float e1 = __expf(acc[mt][nt][1] * scale);
                float e2 = __expf(acc[mt][nt][2] * scale);
                float e3 = __expf(acc[mt][nt][3] * scale);
                *(__nv_bfloat162*)(op + (long long)r0 * Ntot + cg)       = __floats2bfloat162_rn(e0, e1);
                *(__nv_bfloat162*)(op + (long long)(r0 + 8) * Ntot + cg) = __floats2bfloat162_rn(e2, e3);
                rs0 += e0 + e1; rs1 += e2 + e3;
            }
            rs0 += __shfl_xor_sync(0xffffffffu, rs0, 1);
            rs0 += __shfl_xor_sync(0xffffffffu, rs0, 2);
            rs1 += __shfl_xor_sync(0xffffffffu, rs1, 1);
            rs1 += __shfl_xor_sync(0xffffffffu, rs1, 2);
            if (tig == 0) {
                atomicAdd(rowsum + bz * HW + r0, rs0);
                atomicAdd(rowsum + bz * HW + r0 + 8, rs1);
            }
        } else if (MODE == 3) {
            const float inv0 = 1.f / rowsum[bz * HW + r0];
            const float inv1 = 1.f / rowsum[bz * HW + r0 + 8];
            __nv_bfloat16* op = (__nv_bfloat16*)Out + bz * sO;
#pragma unroll
            for (int nt = 0; nt < 8; nt++) {
                const int cg = bx * 128 + warp_n * 64 + nt * 8 + tig * 2;
                *(__nv_bfloat162*)(op + (long long)r0 * Ntot + cg) =
                    __floats2bfloat162_rn(acc[mt][nt][0] * inv0, acc[mt][nt][1] * inv0);
                *(__nv_bfloat162*)(op + (long long)(r0 + 8) * Ntot + cg) =
                    __floats2bfloat162_rn(acc[mt][nt][2] * inv1, acc[mt][nt][3] * inv1);
            }
        } else if (MODE == 2) {
#pragma unroll
            for (int nt = 0; nt < 8; nt++) {
                const int cg = bx * 128 + warp_n * 64 + nt * 8 + tig * 2;
                float b0 = bias[cg], b1 = bias[cg + 1];
                {
                    long long idx = bz * sO + (long long)r0 * Ntot + cg;
                    const float2 rv = *(const float2*)(residual + idx);
                    float2 v = { acc[mt][nt][0] * scale + b0 + rv.x,
                                 acc[mt][nt][1] * scale + b1 + rv.y };
                    *(float2*)((float*)Out + idx) = v;
                }
                {
                    long long idx = bz * sO + (long long)(r0 + 8) * Ntot + cg;
                    const float2 rv = *(const float2*)(residual + idx);
                    float2 v = { acc[mt][nt][2] * scale + b0 + rv.x,
                                 acc[mt][nt][3] * scale + b1 + rv.y };
                    *(float2*)((float*)Out + idx) = v;
                }
            }
        } else {
            __nv_bfloat16* op = (__nv_bfloat16*)Out + bz * sO;
#pragma unroll
            for (int nt = 0; nt < 8; nt++) {
                const int cg = bx * 128 + warp_n * 64 + nt * 8 + tig * 2;
                float b0 = 0.f, b1 = 0.f;
                if (bias) { b0 = bias[cg]; b1 = bias[cg + 1]; }
                *(__nv_bfloat162*)(op + (long long)r0 * Ntot + cg) =
                    __floats2bfloat162_rn(acc[mt][nt][0] * scale + b0, acc[mt][nt][1] * scale + b1);
                *(__nv_bfloat162*)(op + (long long)(r0 + 8) * Ntot + cg) =
                    __floats2bfloat162_rn(acc[mt][nt][2] * scale + b0, acc[mt][nt][3] * scale + b1);
            }
        }
    }
}

// ---------------- launch ----------------
extern "C" void kernel_launch(void* const* d_in, const int* in_sizes, int n_in,
                              void* d_out, int out_size)
{
    const float* x  = (const float*)d_in[0];
    const float* ns = (const float*)d_in[1];
    const float* nb = (const float*)d_in[2];
    const float* wq = (const float*)d_in[3];
    const float* bq = (const float*)d_in[4];
    const float* wk = (const float*)d_in[5];
    const float* bk = (const float*)d_in[6];
    const float* wv = (const float*)d_in[7];
    const float* bv = (const float*)d_in[8];
    const float* wp = (const float*)d_in[9];
    const float* bp = (const float*)d_in[10];
    float* out = (float*)d_out;

    __nv_bfloat16 *hn, *qkv, *s, *o, *wqkvB, *wpB;
    float *bqkv, *rs, *mean, *rstd;
    cudaGetSymbolAddress((void**)&hn,    g_hn);
    cudaGetSymbolAddress((void**)&qkv,   g_qkv);
    cudaGetSymbolAddress((void**)&s,     g_s);
    cudaGetSymbolAddress((void**)&o,     g_o);
    cudaGetSymbolAddress((void**)&wqkvB, g_wqkv);
    cudaGetSymbolAddress((void**)&wpB,   g_wp);
    cudaGetSymbolAddress((void**)&bqkv,  g_bqkv);
    cudaGetSymbolAddress((void**)&rs,    g_rowsum);
    cudaGetSymbolAddress((void**)&mean,  g_mean);
    cudaGetSymbolAddress((void**)&rstd,  g_rstd);

    const int SMEM = NSTG * STAGE;   // 110592
    cudaFuncSetAttribute(mma_gemm<true, 0>,  cudaFuncAttributeMaxDynamicSharedMemorySize, SMEM);
    cudaFuncSetAttribute(mma_gemm<false, 1>, cudaFuncAttributeMaxDynamicSharedMemorySize, SMEM);
    cudaFuncSetAttribute(mma_gemm<true, 2>,  cudaFuncAttributeMaxDynamicSharedMemorySize, SMEM);
    cudaFuncSetAttribute(mma_gemm<true, 3>,  cudaFuncAttributeMaxDynamicSharedMemorySize, SMEM);

    pack_qkvw_kernel<<<(C * NQKV / 4 + 255) / 256, 256>>>(wq, wk, wv, wqkvB);
    pack_misc_kernel<<<(C * C / 4 + 255) / 256, 256>>>(bq, bk, bv, bqkv, wp, wpB);
    zero_rs_kernel<<<(BATCH * HW + 255) / 256, 256>>>(rs);

    // groupnorm (split: strided stats + coalesced apply)
    gn_stats_kernel<<<BATCH * GROUPS, 256>>>(x, mean, rstd);
    gn_apply_kernel<<<(int)(((long long)M_TOT * C / 4 + 255) / 256), 256>>>(x, ns, nb, mean, rstd, hn);

    // fused qkv projection: [32768,512] @ [512,1536]
    {
        dim3 grid(NQKV / 128, M_TOT / 128, 1);
        mma_gemm<true, 0><<<grid, 256, SMEM>>>(hn, wqkvB, bqkv, nullptr, nullptr, qkv,
                                               C, C, NQKV, NQKV, 1.f, 0, 0, 0);
    }

    const __nv_bfloat16* q = qkv;
    const __nv_bfloat16* k = qkv + 512;
    const __nv_bfloat16* v = qkv + 1024;
    const long long sQKV = (long long)HW * NQKV;

    // exp-scores = exp(q @ k^T * c^-0.5), rowsum accumulated via atomics
    {
        dim3 grid(HW / 128, HW / 128, BATCH);
        mma_gemm<false, 1><<<grid, 256, SMEM>>>(q, k, nullptr, nullptr, rs, s,
                                                C, NQKV, NQKV, HW, 1.f / sqrtf((float)C),
                                                sQKV, sQKV, (long long)HW * HW);
    }

    // o = (expS @ v) / Z
    {
        dim3 grid(C / 128, HW / 128, BATCH);
        mma_gemm<true, 3><<<grid, 256, SMEM>>>(s, v, nullptr, nullptr, rs, o,
                                               HW, HW, NQKV, C, 1.f,
                                               (long long)HW * HW, sQKV, (long long)HW * C);
    }

    // out = o @ wp + bp + x
    {
        dim3 grid(C / 128, M_TOT / 128, 1);
        mma_gemm<true, 2><<<grid, 256, SMEM>>>(o, wpB, bp, x, nullptr, out,
                                               C, C, C, C, 1.f, 0, 0, 0);
    }
}

// round 8
// speedup vs baseline: 1.0247x; 1.0247x over previous
#include <cuda_runtime.h>
#include <cuda_bf16.h>
#include <cstdint>
#include <math.h>

// ---------------- problem constants ----------------
#define BATCH 32
#define HW    1024
#define C     512
#define GROUPS 32
#define CPG   16
#define M_TOT (BATCH*HW)       // 32768
#define EPS   1e-6f
#define NQKV  1536

// ---------------- scratch ----------------
__device__ __nv_bfloat16 g_hn  [(long long)M_TOT * C];
__device__ __nv_bfloat16 g_qkv [(long long)M_TOT * NQKV];    // [row][q|k|v]
__device__ __nv_bfloat16 g_s   [(long long)BATCH * HW * HW]; // exp(scores), unnormalized
__device__ __nv_bfloat16 g_o   [(long long)M_TOT * C];
__device__ __nv_bfloat16 g_wqkv[(long long)C * NQKV];        // [k][q|k|v]
__device__ __nv_bfloat16 g_wp  [(long long)C * C];
__device__ float g_bqkv[NQKV];
__device__ float g_rowsum[BATCH * HW];

// ---------------- helpers ----------------
__device__ __forceinline__ uint32_t smem_u32(const void* p) {
    uint32_t a;
    asm("{ .reg .u64 t; cvta.to.shared.u64 t, %1; cvt.u32.u64 %0, t; }" : "=r"(a) : "l"(p));
    return a;
}
#define LDSM_X4(r0,r1,r2,r3,addr) \
    asm volatile("ldmatrix.sync.aligned.m8n8.x4.shared.b16 {%0,%1,%2,%3}, [%4];" \
        : "=r"(r0),"=r"(r1),"=r"(r2),"=r"(r3) : "r"(addr))
#define LDSM_X4T(r0,r1,r2,r3,addr) \
    asm volatile("ldmatrix.sync.aligned.m8n8.x4.trans.shared.b16 {%0,%1,%2,%3}, [%4];" \
        : "=r"(r0),"=r"(r1),"=r"(r2),"=r"(r3) : "r"(addr))
#define MMA_BF16(d, a, b) \
    asm volatile("mma.sync.aligned.m16n8k16.row.col.f32.bf16.bf16.f32 " \
        "{%0,%1,%2,%3}, {%4,%5,%6,%7}, {%8,%9}, {%0,%1,%2,%3};" \
        : "+f"((d)[0]), "+f"((d)[1]), "+f"((d)[2]), "+f"((d)[3]) \
        : "r"((a)[0]), "r"((a)[1]), "r"((a)[2]), "r"((a)[3]), "r"((b)[0]), "r"((b)[1]))
#define CP_ASYNC16(smem, gmem) \
    asm volatile("cp.async.cg.shared.global [%0], [%1], 16;" :: "r"(smem), "l"(gmem))
#define CP_COMMIT() asm volatile("cp.async.commit_group;" ::: "memory")
#define CP_WAIT1()  asm volatile("cp.async.wait_group 1;" ::: "memory")

// ---------------- fused groupnorm (stats + apply), one block per (b,g) ----------------
__global__ __launch_bounds__(256)
void gn_fused_kernel(const float* __restrict__ x, const float* __restrict__ scale,
                     const float* __restrict__ bias, __nv_bfloat16* __restrict__ hn)
{
    int bg = blockIdx.x, b = bg >> 5, g = bg & 31;
    const float4* base4 = reinterpret_cast<const float4*>(x + (long long)b * HW * C + g * CPG);

    float s = 0.f, s2 = 0.f;
    for (int e = threadIdx.x; e < HW * 4; e += 256) {
        int p = e >> 2, cc = e & 3;
        float4 v = base4[(long long)p * 128 + cc];
        s  += v.x + v.y + v.z + v.w;
        s2 += v.x * v.x + v.y * v.y + v.z * v.z + v.w * v.w;
    }
    __shared__ float sh1[256], sh2[256];
    __shared__ float smr[2];
    sh1[threadIdx.x] = s; sh2[threadIdx.x] = s2;
    __syncthreads();
    for (int off = 128; off > 0; off >>= 1) {
        if (threadIdx.x < off) { sh1[threadIdx.x] += sh1[threadIdx.x + off]; sh2[threadIdx.x] += sh2[threadIdx.x + off]; }
        __syncthreads();
    }
    if (threadIdx.x == 0) {
        float m = sh1[0] * (1.f / (HW * CPG));
        float var = sh2[0] * (1.f / (HW * CPG)) - m * m;
        smr[0] = m; smr[1] = rsqrtf(var + EPS);
    }
    __syncthreads();
    const float m = smr[0], r = smr[1];

    __nv_bfloat16* hbase = hn + (long long)b * HW * C + g * CPG;
    for (int e = threadIdx.x; e < HW * 4; e += 256) {
        int p = e >> 2, cc = e & 3;
        float4 v  = base4[(long long)p * 128 + cc];
        float4 sc = reinterpret_cast<const float4*>(scale)[g * 4 + cc];
        float4 bi = reinterpret_cast<const float4*>(bias)[g * 4 + cc];
        __nv_bfloat162 h0 = __floats2bfloat162_rn((v.x - m) * r * sc.x + bi.x, (v.y - m) * r * sc.y + bi.y);
        __nv_bfloat162 h1 = __floats2bfloat162_rn((v.z - m) * r * sc.z + bi.z, (v.w - m) * r * sc.w + bi.w);
        __nv_bfloat162* hp = reinterpret_cast<__nv_bfloat162*>(hbase + (long long)p * C + cc * 4);
        hp[0] = h0; hp[1] = h1;
    }
}

// ---------------- merged prologue: pack qkv weights + biases + wp + zero rowsum ----------------
// blocks [0,768): qkv weight pack; [768,1024): wp pack + bias pack; [1024,1152): zero rowsum
__global__ __launch_bounds__(256)
void prologue_kernel(const float* __restrict__ wq, const float* __restrict__ wk,
                     const float* __restrict__ wv, __nv_bfloat16* __restrict__ wqkvo,
                     const float* __restrict__ bq, const float* __restrict__ bk,
                     const float* __restrict__ bv, float* __restrict__ bqkv,
                     const float* __restrict__ wp, __nv_bfloat16* __restrict__ wpo,
                     float* __restrict__ rs)
{
    int blk = blockIdx.x;
    if (blk < 768) {
        int i = blk * 256 + threadIdx.x;               // float4 over [512][1536]
        int row = i / (NQKV / 4);
        int col = (i % (NQKV / 4)) * 4;
        int sel = col >> 9;
        const float* src = (sel == 0) ? wq : (sel == 1) ? wk : wv;
        float4 v = *reinterpret_cast<const float4*>(src + (long long)row * C + (col & 511));
        __nv_bfloat162* h2 = reinterpret_cast<__nv_bfloat162*>(wqkvo) + i * 2;
        h2[0] = __floats2bfloat162_rn(v.x, v.y);
        h2[1] = __floats2bfloat162_rn(v.z, v.w);
    } else if (blk < 1024) {
        int i = (blk - 768) * 256 + threadIdx.x;       // float4 over [512][512]
        float4 v = reinterpret_cast<const float4*>(wp)[i];
        __nv_bfloat162* h2 = reinterpret_cast<__nv_bfloat162*>(wpo) + i * 2;
        h2[0] = __floats2bfloat162_rn(v.x, v.y);
        h2[1] = __floats2bfloat162_rn(v.z, v.w);
        if (i < NQKV) {
            int sel = i >> 9;
            const float* src = (sel == 0) ? bq : (sel == 1) ? bk : bv;
            bqkv[i] = src[i & 511];
        }
    } else {
        int i = (blk - 1024) * 256 + threadIdx.x;
        if (i < BATCH * HW) rs[i] = 0.f;
    }
}

// ---------------- HMMA GEMM (256 threads, 8 warps of 32x64, 2-stage — R6 config) ----------------
// TB=false (NT): D = A[M,K] @ B[N,K]^T.  TB=true (NN): D = A[M,K] @ B[K,N].
// MODE 0: bf16 out + bias.
// MODE 1: bf16 out = exp(acc*scale), atomicAdd per-row sums into rowsum.
// MODE 2: fp32 out + bias + residual.
// MODE 3: bf16 out = acc / rowsum[row].
#define A_STRIDE 144u
#define BNN_STRIDE 272u
#define BOFF  18432u
#define STAGE 36864u
#define NSTG  2

template<bool TB, int MODE>
__global__ void __launch_bounds__(256, 2)
mma_gemm(const __nv_bfloat16* __restrict__ A, const __nv_bfloat16* __restrict__ B,
         const float* __restrict__ bias, const float* __restrict__ residual,
         float* __restrict__ rowsum,
         void* __restrict__ Out, int K, int lda, int ldb, int Ntot,
         float scale, long long sA, long long sB, long long sO)
{
    extern __shared__ char dyn[];
    const uint32_t smem0 = smem_u32(dyn);

    const int tid = threadIdx.x, lane = tid & 31, wid = tid >> 5;
    const int warp_m = wid & 3, warp_n = wid >> 2;
    const int bx = blockIdx.x, by = blockIdx.y, bz = blockIdx.z;

    const char* gA = (const char*)(A + bz * sA);
    const char* gB = (const char*)(B + bz * sB);

    const int NC = K >> 6;

    float acc[2][8][4];
#pragma unroll
    for (int mt = 0; mt < 2; mt++)
#pragma unroll
        for (int nt = 0; nt < 8; nt++)
#pragma unroll
            for (int e = 0; e < 4; e++) acc[mt][nt][e] = 0.f;

    auto load_chunk = [&](int ci) {
        const uint32_t st = smem0 + (uint32_t)(ci & (NSTG - 1)) * STAGE;
#pragma unroll
        for (int rep = 0; rep < 4; rep++) {
            int c = tid + rep * 256;
            int row = c >> 3, cc = c & 7;
            uint32_t sa = st + (uint32_t)row * A_STRIDE + (uint32_t)cc * 16;
            const char* ga = gA + ((long long)(by * 128 + row) * lda) * 2 + (long long)ci * 128 + cc * 16;
            CP_ASYNC16(sa, ga);
        }
        if (TB) {
#pragma unroll
            for (int rep = 0; rep < 4; rep++) {
                int c = tid + rep * 256;
                int row = c >> 4, cc = c & 15;
                uint32_t sb = st + BOFF + (uint32_t)row * BNN_STRIDE + (uint32_t)cc * 16;
                const char* gb = gB + (((long long)(ci * 64 + row) * ldb) + bx * 128) * 2 + cc * 16;
                CP_ASYNC16(sb, gb);
            }
        } else {
#pragma unroll
            for (int rep = 0; rep < 4; rep++) {
                int c = tid + rep * 256;
                int row = c >> 3, cc = c & 7;
                uint32_t sb = st + BOFF + (uint32_t)row * A_STRIDE + (uint32_t)cc * 16;
                const char* gb = gB + ((long long)(bx * 128 + row) * ldb) * 2 + (long long)ci * 128 + cc * 16;
                CP_ASYNC16(sb, gb);
            }
        }
        CP_COMMIT();
    };

    load_chunk(0);
    load_chunk(1);

    const int lan15 = lane & 15;
    const int hi8   = (lane >> 4) << 3;

    for (int i = 0; i < NC; ++i) {
        CP_WAIT1();
        __syncthreads();
        const uint32_t smA = smem0 + (uint32_t)(i & (NSTG - 1)) * STAGE;
        const uint32_t smB = smA + BOFF;
#pragma unroll
        for (int ks = 0; ks < 4; ks++) {
            uint32_t a[2][4];
#pragma unroll
            for (int mt = 0; mt < 2; mt++) {
                uint32_t ad = smA + (uint32_t)(warp_m * 32 + mt * 16 + lan15) * A_STRIDE
                                  + (uint32_t)(ks * 16 + hi8) * 2;
                LDSM_X4(a[mt][0], a[mt][1], a[mt][2], a[mt][3], ad);
            }
            uint32_t b[8][2];
            if (TB) {
#pragma unroll
                for (int np = 0; np < 4; np++) {
                    uint32_t ad = smB + (uint32_t)(ks * 16 + lan15) * BNN_STRIDE
                                      + (uint32_t)(warp_n * 64 + np * 16 + hi8) * 2;
                    uint32_t r0, r1, r2, r3;
                    LDSM_X4T(r0, r1, r2, r3, ad);
                    b[2*np][0] = r0; b[2*np][1] = r1;
                    b[2*np+1][0] = r2; b[2*np+1][1] = r3;
                }
            } else {
#pragma unroll
                for (int np = 0; np < 4; np++) {
                    uint32_t ad = smB + (uint32_t)(warp_n * 64 + np * 16 + lan15) * A_STRIDE
                                      + (uint32_t)(ks * 16 + hi8) * 2;
                    uint32_t r0, r1, r2, r3;
                    LDSM_X4(r0, r1, r2, r3, ad);
                    b[2*np][0] = r0; b[2*np][1] = r2;
                    b[2*np+1][0] = r1; b[2*np+1][1] = r3;
                }
            }
#pragma unroll
            for (int mt = 0; mt < 2; mt++)
#pragma unroll
                for (int nt = 0; nt < 8; nt++)
                    MMA_BF16(acc[mt][nt], a[mt], b[nt]);
        }
        __syncthreads();
        int nc = i + 2;
        if (nc < NC) load_chunk(nc);
        else CP_COMMIT();
    }

    // ---------------- epilogue ----------------
    const int group = lane >> 2, tig = lane & 3;
#pragma unroll
    for (int mt = 0; mt < 2; mt++) {
        const int r0 = by * 128 + warp_m * 32 + mt * 16 + group;
        if (MODE == 1) {
            __nv_bfloat16* op = (__nv_bfloat16*)Out + bz * sO;
            float rs0 = 0.f, rs1 = 0.f;
#pragma unroll
            for (int nt = 0; nt < 8; nt++) {
                const int cg = bx * 128 + warp_n * 64 + nt * 8 + tig * 2;
                float e0 = __expf(acc[mt][nt][0] * scale);
                float e1 = __expf(acc[mt][nt][1] * scale);
                float e2 = __expf(acc[mt][nt][2] * scale);
                float e3 = __expf(acc[mt][nt][3] * scale);
                *(__nv_bfloat162*)(op + (long long)r0 * Ntot + cg)       = __floats2bfloat162_rn(e0, e1);
                *(__nv_bfloat162*)(op + (long long)(r0 + 8) * Ntot + cg) = __floats2bfloat162_rn(e2, e3);
                rs0 += e0 + e1; rs1 += e2 + e3;
            }
            rs0 += __shfl_xor_sync(0xffffffffu, rs0, 1);
            rs0 += __shfl_xor_sync(0xffffffffu, rs0, 2);
            rs1 += __shfl_xor_sync(0xffffffffu, rs1, 1);
            rs1 += __shfl_xor_sync(0xffffffffu, rs1, 2);
            if (tig == 0) {
                atomicAdd(rowsum + bz * HW + r0, rs0);
                atomicAdd(rowsum + bz * HW + r0 + 8, rs1);
            }
        } else if (MODE == 3) {
            const float inv0 = 1.f / rowsum[bz * HW + r0];
            const float inv1 = 1.f / rowsum[bz * HW + r0 + 8];
            __nv_bfloat16* op = (__nv_bfloat16*)Out + bz * sO;
#pragma unroll
            for (int nt = 0; nt < 8; nt++) {
                const int cg = bx * 128 + warp_n * 64 + nt * 8 + tig * 2;
                *(__nv_bfloat162*)(op + (long long)r0 * Ntot + cg) =
                    __floats2bfloat162_rn(acc[mt][nt][0] * inv0, acc[mt][nt][1] * inv0);
                *(__nv_bfloat162*)(op + (long long)(r0 + 8) * Ntot + cg) =
                    __floats2bfloat162_rn(acc[mt][nt][2] * inv1, acc[mt][nt][3] * inv1);
            }
        } else if (MODE == 2) {
#pragma unroll
            for (int nt = 0; nt < 8; nt++) {
                const int cg = bx * 128 + warp_n * 64 + nt * 8 + tig * 2;
                float b0 = bias[cg], b1 = bias[cg + 1];
                {
                    long long idx = bz * sO + (long long)r0 * Ntot + cg;
                    const float2 rv = *(const float2*)(residual + idx);
                    float2 v = { acc[mt][nt][0] * scale + b0 + rv.x,
                                 acc[mt][nt][1] * scale + b1 + rv.y };
                    *(float2*)((float*)Out + idx) = v;
                }
                {
                    long long idx = bz * sO + (long long)(r0 + 8) * Ntot + cg;
                    const float2 rv = *(const float2*)(residual + idx);
                    float2 v = { acc[mt][nt][2] * scale + b0 + rv.x,
                                 acc[mt][nt][3] * scale + b1 + rv.y };
                    *(float2*)((float*)Out + idx) = v;
                }
            }
        } else {
            __nv_bfloat16* op = (__nv_bfloat16*)Out + bz * sO;
#pragma unroll
            for (int nt = 0; nt < 8; nt++) {
                const int cg = bx * 128 + warp_n * 64 + nt * 8 + tig * 2;
                float b0 = bias[cg], b1 = bias[cg + 1];
                *(__nv_bfloat162*)(op + (long long)r0 * Ntot + cg) =
                    __floats2bfloat162_rn(acc[mt][nt][0] + b0, acc[mt][nt][1] + b1);
                *(__nv_bfloat162*)(op + (long long)(r0 + 8) * Ntot + cg) =
                    __floats2bfloat162_rn(acc[mt][nt][2] + b0, acc[mt][nt][3] + b1);
            }
        }
    }
}

// ---------------- launch ----------------
extern "C" void kernel_launch(void* const* d_in, const int* in_sizes, int n_in,
                              void* d_out, int out_size)
{
    const float* x  = (const float*)d_in[0];
    const float* ns = (const float*)d_in[1];
    const float* nb = (const float*)d_in[2];
    const float* wq = (const float*)d_in[3];
    const float* bq = (const float*)d_in[4];
    const float* wk = (const float*)d_in[5];
    const float* bk = (const float*)d_in[6];
    const float* wv = (const float*)d_in[7];
    const float* bv = (const float*)d_in[8];
    const float* wp = (const float*)d_in[9];
    const float* bp = (const float*)d_in[10];
    float* out = (float*)d_out;

    __nv_bfloat16 *hn, *qkv, *s, *o, *wqkvB, *wpB;
    float *bqkv, *rs;
    cudaGetSymbolAddress((void**)&hn,    g_hn);
    cudaGetSymbolAddress((void**)&qkv,   g_qkv);
    cudaGetSymbolAddress((void**)&s,     g_s);
    cudaGetSymbolAddress((void**)&o,     g_o);
    cudaGetSymbolAddress((void**)&wqkvB, g_wqkv);
    cudaGetSymbolAddress((void**)&wpB,   g_wp);
    cudaGetSymbolAddress((void**)&bqkv,  g_bqkv);
    cudaGetSymbolAddress((void**)&rs,    g_rowsum);

    const int SMEM = NSTG * STAGE;   // 73728
    cudaFuncSetAttribute(mma_gemm<true, 0>,  cudaFuncAttributeMaxDynamicSharedMemorySize, SMEM);
    cudaFuncSetAttribute(mma_gemm<false, 1>, cudaFuncAttributeMaxDynamicSharedMemorySize, SMEM);
    cudaFuncSetAttribute(mma_gemm<true, 2>,  cudaFuncAttributeMaxDynamicSharedMemorySize, SMEM);
    cudaFuncSetAttribute(mma_gemm<true, 3>,  cudaFuncAttributeMaxDynamicSharedMemorySize, SMEM);

    // merged prologue (weight packs + bias pack + rowsum zero)
    prologue_kernel<<<1152, 256>>>(wq, wk, wv, wqkvB, bq, bk, bv, bqkv, wp, wpB, rs);

    // fused groupnorm
    gn_fused_kernel<<<BATCH * GROUPS, 256>>>(x, ns, nb, hn);

    // fused qkv projection: [32768,512] @ [512,1536]
    {
        dim3 grid(NQKV / 128, M_TOT / 128, 1);
        mma_gemm<true, 0><<<grid, 256, SMEM>>>(hn, wqkvB, bqkv, nullptr, nullptr, qkv,
                                               C, C, NQKV, NQKV, 1.f, 0, 0, 0);
    }

    const __nv_bfloat16* q = qkv;
    const __nv_bfloat16* k = qkv + 512;
    const __nv_bfloat16* v = qkv + 1024;
    const long long sQKV = (long long)HW * NQKV;

    // exp-scores = exp(q @ k^T * c^-0.5), rowsum accumulated via atomics
    {
        dim3 grid(HW / 128, HW / 128, BATCH);
        mma_gemm<false, 1><<<grid, 256, SMEM>>>(q, k, nullptr, nullptr, rs, s,
                                                C, NQKV, NQKV, HW, 1.f / sqrtf((float)C),
                                                sQKV, sQKV, (long long)HW * HW);
    }

    // o = (expS @ v) / Z
    {
        dim3 grid(C / 128, HW / 128, BATCH);
        mma_gemm<true, 3><<<grid, 256, SMEM>>>(s, v, nullptr, nullptr, rs, o,
                                               HW, HW, NQKV, C, 1.f,
                                               (long long)HW * HW, sQKV, (long long)HW * C);
    }

    // out = o @ wp + bp + x
    {
        dim3 grid(C / 128, M_TOT / 128, 1);
        mma_gemm<true, 2><<<grid, 256, SMEM>>>(o, wpB, bp, x, nullptr, out,
                                               C, C, C, C, 1.f, 0, 0, 0);
    }
}

// round 9
// speedup vs baseline: 1.0627x; 1.0371x over previous
#include <cuda_runtime.h>
#include <cuda_bf16.h>
#include <cstdint>
#include <math.h>

// ---------------- problem constants ----------------
#define BATCH 32
#define HW    1024
#define C     512
#define GROUPS 32
#define CPG   16
#define M_TOT (BATCH*HW)       // 32768
#define EPS   1e-6f
#define NQKV  1536

// ---------------- scratch ----------------
__device__ __nv_bfloat16 g_hn  [(long long)M_TOT * C];
__device__ __nv_bfloat16 g_qkv [(long long)M_TOT * NQKV];    // [row][q|k|v]
__device__ __nv_bfloat16 g_s   [(long long)BATCH * HW * HW]; // exp(scores), unnormalized
__device__ __nv_bfloat16 g_o   [(long long)M_TOT * C];
__device__ __nv_bfloat16 g_wqkv[(long long)C * NQKV];        // [k][q|k|v]
__device__ __nv_bfloat16 g_wp  [(long long)C * C];
__device__ float g_bqkv[NQKV];
__device__ float g_rowsum[BATCH * HW];

// ---------------- helpers ----------------
__device__ __forceinline__ uint32_t smem_u32(const void* p) {
    uint32_t a;
    asm("{ .reg .u64 t; cvta.to.shared.u64 t, %1; cvt.u32.u64 %0, t; }" : "=r"(a) : "l"(p));
    return a;
}
#define LDSM_X4(r0,r1,r2,r3,addr) \
    asm volatile("ldmatrix.sync.aligned.m8n8.x4.shared.b16 {%0,%1,%2,%3}, [%4];" \
        : "=r"(r0),"=r"(r1),"=r"(r2),"=r"(r3) : "r"(addr))
#define LDSM_X4T(r0,r1,r2,r3,addr) \
    asm volatile("ldmatrix.sync.aligned.m8n8.x4.trans.shared.b16 {%0,%1,%2,%3}, [%4];" \
        : "=r"(r0),"=r"(r1),"=r"(r2),"=r"(r3) : "r"(addr))
#define MMA_BF16(d, a, b) \
    asm volatile("mma.sync.aligned.m16n8k16.row.col.f32.bf16.bf16.f32 " \
        "{%0,%1,%2,%3}, {%4,%5,%6,%7}, {%8,%9}, {%0,%1,%2,%3};" \
        : "+f"((d)[0]), "+f"((d)[1]), "+f"((d)[2]), "+f"((d)[3]) \
        : "r"((a)[0]), "r"((a)[1]), "r"((a)[2]), "r"((a)[3]), "r"((b)[0]), "r"((b)[1]))
#define CP_ASYNC16(smem, gmem) \
    asm volatile("cp.async.cg.shared.global [%0], [%1], 16;" :: "r"(smem), "l"(gmem))
#define CP_COMMIT() asm volatile("cp.async.commit_group;" ::: "memory")
#define CP_WAIT1()  asm volatile("cp.async.wait_group 1;" ::: "memory")

// ---------------- fused groupnorm (stats + apply), one block per (b,g) ----------------
__global__ __launch_bounds__(256)
void gn_fused_kernel(const float* __restrict__ x, const float* __restrict__ scale,
                     const float* __restrict__ bias, __nv_bfloat16* __restrict__ hn)
{
    int bg = blockIdx.x, b = bg >> 5, g = bg & 31;
    const float4* base4 = reinterpret_cast<const float4*>(x + (long long)b * HW * C + g * CPG);

    float s = 0.f, s2 = 0.f;
    for (int e = threadIdx.x; e < HW * 4; e += 256) {
        int p = e >> 2, cc = e & 3;
        float4 v = base4[(long long)p * 128 + cc];
        s  += v.x + v.y + v.z + v.w;
        s2 += v.x * v.x + v.y * v.y + v.z * v.z + v.w * v.w;
    }
    __shared__ float sh1[256], sh2[256];
    __shared__ float smr[2];
    sh1[threadIdx.x] = s; sh2[threadIdx.x] = s2;
    __syncthreads();
    for (int off = 128; off > 0; off >>= 1) {
        if (threadIdx.x < off) { sh1[threadIdx.x] += sh1[threadIdx.x + off]; sh2[threadIdx.x] += sh2[threadIdx.x + off]; }
        __syncthreads();
    }
    if (threadIdx.x == 0) {
        float m = sh1[0] * (1.f / (HW * CPG));
        float var = sh2[0] * (1.f / (HW * CPG)) - m * m;
        smr[0] = m; smr[1] = rsqrtf(var + EPS);
    }
    __syncthreads();
    const float m = smr[0], r = smr[1];

    __nv_bfloat16* hbase = hn + (long long)b * HW * C + g * CPG;
    for (int e = threadIdx.x; e < HW * 4; e += 256) {
        int p = e >> 2, cc = e & 3;
        float4 v  = base4[(long long)p * 128 + cc];
        float4 sc = reinterpret_cast<const float4*>(scale)[g * 4 + cc];
        float4 bi = reinterpret_cast<const float4*>(bias)[g * 4 + cc];
        __nv_bfloat162 h0 = __floats2bfloat162_rn((v.x - m) * r * sc.x + bi.x, (v.y - m) * r * sc.y + bi.y);
        __nv_bfloat162 h1 = __floats2bfloat162_rn((v.z - m) * r * sc.z + bi.z, (v.w - m) * r * sc.w + bi.w);
        __nv_bfloat162* hp = reinterpret_cast<__nv_bfloat162*>(hbase + (long long)p * C + cc * 4);
        hp[0] = h0; hp[1] = h1;
    }
}

// ---------------- merged prologue: pack qkv weights + biases + wp + zero rowsum ----------------
__global__ __launch_bounds__(256)
void prologue_kernel(const float* __restrict__ wq, const float* __restrict__ wk,
                     const float* __restrict__ wv, __nv_bfloat16* __restrict__ wqkvo,
                     const float* __restrict__ bq, const float* __restrict__ bk,
                     const float* __restrict__ bv, float* __restrict__ bqkv,
                     const float* __restrict__ wp, __nv_bfloat16* __restrict__ wpo,
                     float* __restrict__ rs)
{
    int blk = blockIdx.x;
    if (blk < 768) {
        int i = blk * 256 + threadIdx.x;               // float4 over [512][1536]
        int row = i / (NQKV / 4);
        int col = (i % (NQKV / 4)) * 4;
        int sel = col >> 9;
        const float* src = (sel == 0) ? wq : (sel == 1) ? wk : wv;
        float4 v = *reinterpret_cast<const float4*>(src + (long long)row * C + (col & 511));
        __nv_bfloat162* h2 = reinterpret_cast<__nv_bfloat162*>(wqkvo) + i * 2;
        h2[0] = __floats2bfloat162_rn(v.x, v.y);
        h2[1] = __floats2bfloat162_rn(v.z, v.w);
    } else if (blk < 1024) {
        int i = (blk - 768) * 256 + threadIdx.x;       // float4 over [512][512]
        float4 v = reinterpret_cast<const float4*>(wp)[i];
        __nv_bfloat162* h2 = reinterpret_cast<__nv_bfloat162*>(wpo) + i * 2;
        h2[0] = __floats2bfloat162_rn(v.x, v.y);
        h2[1] = __floats2bfloat162_rn(v.z, v.w);
        if (i < NQKV) {
            int sel = i >> 9;
            const float* src = (sel == 0) ? bq : (sel == 1) ? bk : bv;
            bqkv[i] = src[i & 511];
        }
    } else {
        int i = (blk - 1024) * 256 + threadIdx.x;
        if (i < BATCH * HW) rs[i] = 0.f;
    }
}

// ---------------- HMMA GEMM (256 threads, 8 warps of 32x64, 3-stage, 1 sync/iter) ----------------
// TB=false (NT): D = A[M,K] @ B[N,K]^T.  TB=true (NN): D = A[M,K] @ B[K,N].
// MODE 0: bf16 out + bias.
// MODE 1: bf16 out = exp(acc*scale), atomicAdd per-row sums into rowsum.
// MODE 2: fp32 out + bias + residual.
// MODE 3: bf16 out = acc / rowsum[row].
#define A_STRIDE 144u
#define BNN_STRIDE 272u
#define BOFF  18432u
#define STAGE 36864u
#define NSTG  3

template<bool TB, int MODE>
__global__ void __launch_bounds__(256, 2)
mma_gemm(const __nv_bfloat16* __restrict__ A, const __nv_bfloat16* __restrict__ B,
         const float* __restrict__ bias, const float* __restrict__ residual,
         float* __restrict__ rowsum,
         void* __restrict__ Out, int K, int lda, int ldb, int Ntot,
         float scale, long long sA, long long sB, long long sO)
{
    extern __shared__ char dyn[];
    const uint32_t smem0 = smem_u32(dyn);
    const uint32_t smemEnd = smem0 + NSTG * STAGE;

    const int tid = threadIdx.x, lane = tid & 31, wid = tid >> 5;
    const int warp_m = wid & 3, warp_n = wid >> 2;
    const int bx = blockIdx.x, by = blockIdx.y, bz = blockIdx.z;

    const int NC = K >> 6;

    float acc[2][8][4];
#pragma unroll
    for (int mt = 0; mt < 2; mt++)
#pragma unroll
        for (int nt = 0; nt < 8; nt++)
#pragma unroll
            for (int e = 0; e < 4; e++) acc[mt][nt][e] = 0.f;

    // ----- incremental global pointers -----
    const char* pA = (const char*)(A + bz * sA)
                   + ((long long)(by * 128 + (tid >> 3)) * lda) * 2 + (tid & 7) * 16;
    const long long aRep = (long long)32 * lda * 2;   // +32 rows
    const char* pB;
    long long bRep;
    if (TB) {
        pB = (const char*)(B + bz * sB) + ((long long)(tid >> 4) * ldb + bx * 128) * 2 + (tid & 15) * 16;
        bRep = (long long)16 * ldb * 2;               // +16 k-rows
    } else {
        pB = (const char*)(B + bz * sB) + ((long long)(bx * 128 + (tid >> 3)) * ldb) * 2 + (tid & 7) * 16;
        bRep = (long long)32 * ldb * 2;               // +32 n-rows
    }
    const long long aAdv = 128;                        // bytes per k-chunk
    const long long bAdv = TB ? (long long)64 * ldb * 2 : 128;

    // ----- smem store offsets (per-thread constants) -----
    const uint32_t sAoff = (uint32_t)(tid >> 3) * A_STRIDE + (uint32_t)(tid & 7) * 16;
    const uint32_t sBoff = TB
        ? BOFF + (uint32_t)(tid >> 4) * BNN_STRIDE + (uint32_t)(tid & 15) * 16
        : BOFF + (uint32_t)(tid >> 3) * A_STRIDE + (uint32_t)(tid & 7) * 16;
    constexpr uint32_t sBrep = TB ? 16u * BNN_STRIDE : 32u * A_STRIDE;

    uint32_t stLd = smem0;    // stage base for next load
    auto load_chunk = [&]() {
#pragma unroll
        for (int rep = 0; rep < 4; rep++)
            CP_ASYNC16(stLd + sAoff + (uint32_t)rep * (32u * A_STRIDE), pA + rep * aRep);
#pragma unroll
        for (int rep = 0; rep < 4; rep++)
            CP_ASYNC16(stLd + sBoff + (uint32_t)rep * sBrep, pB + rep * bRep);
        CP_COMMIT();
        pA += aAdv; pB += bAdv;
        stLd += STAGE; if (stLd == smemEnd) stLd = smem0;
    };

    load_chunk();
    load_chunk();

    const int lan15 = lane & 15;
    const int hi8   = (lane >> 4) << 3;

    uint32_t smCur = smem0;
    for (int i = 0; i < NC; ++i) {
        CP_WAIT1();
        __syncthreads();
        const uint32_t smA = smCur;
        const uint32_t smB = smCur + BOFF;
#pragma unroll
        for (int ks = 0; ks < 4; ks++) {
            uint32_t a[2][4];
#pragma unroll
            for (int mt = 0; mt < 2; mt++) {
                uint32_t ad = smA + (uint32_t)(warp_m * 32 + mt * 16 + lan15) * A_STRIDE
                                  + (uint32_t)(ks * 16 + hi8) * 2;
                LDSM_X4(a[mt][0], a[mt][1], a[mt][2], a[mt][3], ad);
            }
            uint32_t b[8][2];
            if (TB) {
#pragma unroll
                for (int np = 0; np < 4; np++) {
                    uint32_t ad = smB + (uint32_t)(ks * 16 + lan15) * BNN_STRIDE
                                      + (uint32_t)(warp_n * 64 + np * 16 + hi8) * 2;
                    uint32_t r0, r1, r2, r3;
                    LDSM_X4T(r0, r1, r2, r3, ad);
                    b[2*np][0] = r0; b[2*np][1] = r1;
                    b[2*np+1][0] = r2; b[2*np+1][1] = r3;
                }
            } else {
#pragma unroll
                for (int np = 0; np < 4; np++) {
                    uint32_t ad = smB + (uint32_t)(warp_n * 64 + np * 16 + lan15) * A_STRIDE
                                      + (uint32_t)(ks * 16 + hi8) * 2;
                    uint32_t r0, r1, r2, r3;
                    LDSM_X4(r0, r1, r2, r3, ad);
                    b[2*np][0] = r0; b[2*np][1] = r2;
                    b[2*np+1][0] = r1; b[2*np+1][1] = r3;
                }
            }
#pragma unroll
            for (int mt = 0; mt < 2; mt++)
#pragma unroll
                for (int nt = 0; nt < 8; nt++)
                    MMA_BF16(acc[mt][nt], a[mt], b[nt]);
        }
        smCur += STAGE; if (smCur == smemEnd) smCur = smem0;
        // load AFTER compute: stage (i+2)%3 == (i-1)%3, whose readers all
        // passed the barrier at the top of this iteration. No trailing sync.
        if (i + 2 < NC) load_chunk();
        else CP_COMMIT();
    }

    // ---------------- epilogue ----------------
    const int group = lane >> 2, tig = lane & 3;
#pragma unroll
    for (int mt = 0; mt < 2; mt++) {
        const int r0 = by * 128 + warp_m * 32 + mt * 16 + group;
        if (MODE == 1) {
            __nv_bfloat16* op = (__nv_bfloat16*)Out + bz * sO;
            float rs0 = 0.f, rs1 = 0.f;
#pragma unroll
            for (int nt = 0; nt < 8; nt++) {
                const int cg = bx * 128 + warp_n * 64 + nt * 8 + tig * 2;
                float e0 = __expf(acc[mt][nt][0] * scale);
                float e1 = __expf(acc[mt][nt][1] * scale);
                float e2 = __expf(acc[mt][nt][2] * scale);
                float e3 = __expf(acc[mt][nt][3] * scale);
                *(__nv_bfloat162*)(op + (long long)r0 * Ntot + cg)       = __floats2bfloat162_rn(e0, e1);
                *(__nv_bfloat162*)(op + (long long)(r0 + 8) * Ntot + cg) = __floats2bfloat162_rn(e2, e3);
                rs0 += e0 + e1; rs1 += e2 + e3;
            }
            rs0 += __shfl_xor_sync(0xffffffffu, rs0, 1);
            rs0 += __shfl_xor_sync(0xffffffffu, rs0, 2);
            rs1 += __shfl_xor_sync(0xffffffffu, rs1, 1);
            rs1 += __shfl_xor_sync(0xffffffffu, rs1, 2);
            if (tig == 0) {
                atomicAdd(rowsum + bz * HW + r0, rs0);
                atomicAdd(rowsum + bz * HW + r0 + 8, rs1);
            }
        } else if (MODE == 3) {
            const float inv0 = 1.f / rowsum[bz * HW + r0];
            const float inv1 = 1.f / rowsum[bz * HW + r0 + 8];
            __nv_bfloat16* op = (__nv_bfloat16*)Out + bz * sO;
#pragma unroll
            for (int nt = 0; nt < 8; nt++) {
                const int cg = bx * 128 + warp_n * 64 + nt * 8 + tig * 2;
                *(__nv_bfloat162*)(op + (long long)r0 * Ntot + cg) =
                    __floats2bfloat162_rn(acc[mt][nt][0] * inv0, acc[mt][nt][1] * inv0);
                *(__nv_bfloat162*)(op + (long long)(r0 + 8) * Ntot + cg) =
                    __floats2bfloat162_rn(acc[mt][nt][2] * inv1, acc[mt][nt][3] * inv1);
            }
        } else if (MODE == 2) {
#pragma unroll
            for (int nt = 0; nt < 8; nt++) {
                const int cg = bx * 128 + warp_n * 64 + nt * 8 + tig * 2;
                float b0 = bias[cg], b1 = bias[cg + 1];
                {
                    long long idx = bz * sO + (long long)r0 * Ntot + cg;
                    const float2 rv = *(const float2*)(residual + idx);
                    float2 v = { acc[mt][nt][0] + b0 + rv.x,
                                 acc[mt][nt][1] + b1 + rv.y };
                    *(float2*)((float*)Out + idx) = v;
                }
                {
                    long long idx = bz * sO + (long long)(r0 + 8) * Ntot + cg;
                    const float2 rv = *(const float2*)(residual + idx);
                    float2 v = { acc[mt][nt][2] + b0 + rv.x,
                                 acc[mt][nt][3] + b1 + rv.y };
                    *(float2*)((float*)Out + idx) = v;
                }
            }
        } else {
            __nv_bfloat16* op = (__nv_bfloat16*)Out + bz * sO;
#pragma unroll
            for (int nt = 0; nt < 8; nt++) {
                const int cg = bx * 128 + warp_n * 64 + nt * 8 + tig * 2;
                float b0 = bias[cg], b1 = bias[cg + 1];
                *(__nv_bfloat162*)(op + (long long)r0 * Ntot + cg) =
                    __floats2bfloat162_rn(acc[mt][nt][0] + b0, acc[mt][nt][1] + b1);
                *(__nv_bfloat162*)(op + (long long)(r0 + 8) * Ntot + cg) =
                    __floats2bfloat162_rn(acc[mt][nt][2] + b0, acc[mt][nt][3] + b1);
            }
        }
    }
}

// ---------------- launch ----------------
extern "C" void kernel_launch(void* const* d_in, const int* in_sizes, int n_in,
                              void* d_out, int out_size)
{
    const float* x  = (const float*)d_in[0];
    const float* ns = (const float*)d_in[1];
    const float* nb = (const float*)d_in[2];
    const float* wq = (const float*)d_in[3];
    const float* bq = (const float*)d_in[4];
    const float* wk = (const float*)d_in[5];
    const float* bk = (const float*)d_in[6];
    const float* wv = (const float*)d_in[7];
    const float* bv = (const float*)d_in[8];
    const float* wp = (const float*)d_in[9];
    const float* bp = (const float*)d_in[10];
    float* out = (float*)d_out;

    __nv_bfloat16 *hn, *qkv, *s, *o, *wqkvB, *wpB;
    float *bqkv, *rs;
    cudaGetSymbolAddress((void**)&hn,    g_hn);
    cudaGetSymbolAddress((void**)&qkv,   g_qkv);
    cudaGetSymbolAddress((void**)&s,     g_s);
    cudaGetSymbolAddress((void**)&o,     g_o);
    cudaGetSymbolAddress((void**)&wqkvB, g_wqkv);
    cudaGetSymbolAddress((void**)&wpB,   g_wp);
    cudaGetSymbolAddress((void**)&bqkv,  g_bqkv);
    cudaGetSymbolAddress((void**)&rs,    g_rowsum);

    const int SMEM = NSTG * STAGE;   // 110592
    cudaFuncSetAttribute(mma_gemm<true, 0>,  cudaFuncAttributeMaxDynamicSharedMemorySize, SMEM);
    cudaFuncSetAttribute(mma_gemm<false, 1>, cudaFuncAttributeMaxDynamicSharedMemorySize, SMEM);
    cudaFuncSetAttribute(mma_gemm<true, 2>,  cudaFuncAttributeMaxDynamicSharedMemorySize, SMEM);
    cudaFuncSetAttribute(mma_gemm<true, 3>,  cudaFuncAttributeMaxDynamicSharedMemorySize, SMEM);

    // merged prologue (weight packs + bias pack + rowsum zero)
    prologue_kernel<<<1152, 256>>>(wq, wk, wv, wqkvB, bq, bk, bv, bqkv, wp, wpB, rs);

    // fused groupnorm
    gn_fused_kernel<<<BATCH * GROUPS, 256>>>(x, ns, nb, hn);

    // fused qkv projection: [32768,512] @ [512,1536]
    {
        dim3 grid(NQKV / 128, M_TOT / 128, 1);
        mma_gemm<true, 0><<<grid, 256, SMEM>>>(hn, wqkvB, bqkv, nullptr, nullptr, qkv,
                                               C, C, NQKV, NQKV, 1.f, 0, 0, 0);
    }

    const __nv_bfloat16* q = qkv;
    const __nv_bfloat16* k = qkv + 512;
    const __nv_bfloat16* v = qkv + 1024;
    const long long sQKV = (long long)HW * NQKV;

    // exp-scores = exp(q @ k^T * c^-0.5), rowsum accumulated via atomics
    {
        dim3 grid(HW / 128, HW / 128, BATCH);
        mma_gemm<false, 1><<<grid, 256, SMEM>>>(q, k, nullptr, nullptr, rs, s,
                                                C, NQKV, NQKV, HW, 1.f / sqrtf((float)C),
                                                sQKV, sQKV, (long long)HW * HW);
    }

    // o = (expS @ v) / Z
    {
        dim3 grid(C / 128, HW / 128, BATCH);
        mma_gemm<true, 3><<<grid, 256, SMEM>>>(s, v, nullptr, nullptr, rs, o,
                                               HW, HW, NQKV, C, 1.f,
                                               (long long)HW * HW, sQKV, (long long)HW * C);
    }

    // out = o @ wp + bp + x
    {
        dim3 grid(C / 128, M_TOT / 128, 1);
        mma_gemm<true, 2><<<grid, 256, SMEM>>>(o, wpB, bp, x, nullptr, out,
                                               C, C, C, C, 1.f, 0, 0, 0);
    }
}